// round 4
// baseline (speedup 1.0000x reference)
#include <cuda_runtime.h>
#include <cuda_bf16.h>
#include <cstdint>

#define NB 16384
#define FF 1024
#define DD 256

// ---------- device scratch (no allocation allowed) ----------
__device__ __nv_bfloat16 g_Wp_hi[3 * 256 * 1024];
__device__ __nv_bfloat16 g_Wp_lo[3 * 256 * 1024];
__device__ __nv_bfloat16 g_W2p_hi[3 * 4 * 256 * 64];
__device__ __nv_bfloat16 g_W2p_lo[3 * 4 * 256 * 64];
__device__ __nv_bfloat16 g_h_hi[3ull * NB * 256];
__device__ __nv_bfloat16 g_h_lo[3ull * NB * 256];
__device__ float         g_gates[3ull * NB * 12];

// ---------- helpers ----------
__device__ __forceinline__ unsigned ld_u32(const __nv_bfloat16* p) {
    return *reinterpret_cast<const unsigned*>(p);
}
__device__ __forceinline__ void cp16(void* dst, const void* src) {
    unsigned s = (unsigned)__cvta_generic_to_shared(dst);
    asm volatile("cp.async.cg.shared.global [%0], [%1], 16;\n" :: "r"(s), "l"(src));
}
__device__ __forceinline__ void cp_commit() { asm volatile("cp.async.commit_group;\n"); }
__device__ __forceinline__ void cp_wait0()  { asm volatile("cp.async.wait_group 0;\n"); }

__device__ __forceinline__ void mma_bf16(float* c, const unsigned* a, unsigned b0, unsigned b1) {
    asm volatile(
        "mma.sync.aligned.m16n8k16.row.col.f32.bf16.bf16.f32 "
        "{%0,%1,%2,%3}, {%4,%5,%6,%7}, {%8,%9}, {%0,%1,%2,%3};\n"
        : "+f"(c[0]), "+f"(c[1]), "+f"(c[2]), "+f"(c[3])
        : "r"(a[0]), "r"(a[1]), "r"(a[2]), "r"(a[3]), "r"(b0), "r"(b1));
}

// ---------- weight packing ----------
// W1 pack: [3][n=256][k=1024] bf16 hi/lo, n = e*64 + j, from W1[e][k][j]
__global__ void pack_w1_kernel(const float* __restrict__ W1A,
                               const float* __restrict__ W1S,
                               const float* __restrict__ W1B)
{
    int idx = blockIdx.x * blockDim.x + threadIdx.x;
    if (idx >= 3 * 256 * 1024) return;
    int k = idx & 1023;
    int n = (idx >> 10) & 255;
    int g = idx >> 18;
    const float* W1 = (g == 0) ? W1A : (g == 1) ? W1S : W1B;
    float w = W1[((size_t)(n >> 6) * 1024 + k) * 64 + (n & 63)];
    __nv_bfloat16 hi = __float2bfloat16(w);
    g_Wp_hi[idx] = hi;
    g_Wp_lo[idx] = __float2bfloat16(w - __bfloat162float(hi));
}

// W2 pack: [3][e][d=256][k=64] from W2[e][k][d]
__global__ void pack_w2_kernel(const float* __restrict__ W2A,
                               const float* __restrict__ W2S,
                               const float* __restrict__ W2B)
{
    int idx = blockIdx.x * blockDim.x + threadIdx.x;
    if (idx >= 3 * 4 * 256 * 64) return;
    int k = idx & 63;
    int d = (idx >> 6) & 255;
    int e = (idx >> 14) & 3;
    int g = idx >> 16;
    const float* W2 = (g == 0) ? W2A : (g == 1) ? W2S : W2B;
    float w = W2[((size_t)e * 64 + k) * 256 + d];
    __nv_bfloat16 hi = __float2bfloat16(w);
    g_W2p_hi[idx] = hi;
    g_W2p_lo[idx] = __float2bfloat16(w - __bfloat162float(hi));
}

// ---------- gates: softmax(x @ Wg + bg) ----------
__global__ __launch_bounds__(256)
void gate_kernel(const float* __restrict__ xA, const float* __restrict__ xS,
                 const float* __restrict__ xB,
                 const float* __restrict__ WgA, const float* __restrict__ bgA,
                 const float* __restrict__ WgS, const float* __restrict__ bgS,
                 const float* __restrict__ WgB, const float* __restrict__ bgB)
{
    __shared__ float sWg[12][1024];
    const int g = blockIdx.z;
    const int row0 = blockIdx.x * 64;
    const float* x  = (g == 0) ? xA  : (g == 1) ? xS  : xB;
    const float* Wg = (g == 0) ? WgA : (g == 1) ? WgS : WgB;
    const float* bg = (g == 0) ? bgA : (g == 1) ? bgS : bgB;
    const int G = (g == 1) ? 12 : 8;
    const int tid = threadIdx.x, lane = tid & 31, wid = tid >> 5;

    for (int i = tid; i < G * 1024; i += 256) {
        int j = i >> 10, k = i & 1023;
        sWg[j][k] = Wg[(size_t)k * G + j];
    }
    __syncthreads();

    for (int rr = 0; rr < 8; rr++) {
        int row = row0 + wid * 8 + rr;
        float acc[12];
        #pragma unroll
        for (int j = 0; j < 12; j++) acc[j] = 0.f;
        const float* xr = x + (size_t)row * 1024;
        for (int k = lane; k < 1024; k += 32) {
            float xv = xr[k];
            #pragma unroll
            for (int j = 0; j < 12; j++)
                if (j < G) acc[j] += xv * sWg[j][k];
        }
        #pragma unroll
        for (int j = 0; j < 12; j++) {
            #pragma unroll
            for (int off = 16; off > 0; off >>= 1)
                acc[j] += __shfl_xor_sync(0xffffffffu, acc[j], off);
        }
        if (lane == 0) {
            float lg[12], m = -1e30f;
            for (int j = 0; j < G; j++) { lg[j] = acc[j] + bg[j]; m = fmaxf(m, lg[j]); }
            float s = 0.f;
            for (int j = 0; j < G; j++) { lg[j] = expf(lg[j] - m); s += lg[j]; }
            float inv = 1.f / s;
            float* dst = g_gates + ((size_t)g * NB + row) * 12;
            for (int j = 0; j < G; j++) dst[j] = lg[j] * inv;
        }
    }
}

// ---------- layer 1: h = relu(x @ W1cat + b1), stored split bf16 hi/lo ----------
#define A_BUF 5120   // 128*40 elems per buffer
#define B_BUF 10240  // 256*40

__global__ __launch_bounds__(256, 1)
void layer1_kernel(const float* __restrict__ xA, const float* __restrict__ xS,
                   const float* __restrict__ xB,
                   const float* __restrict__ b1A, const float* __restrict__ b1S,
                   const float* __restrict__ b1B)
{
    extern __shared__ __nv_bfloat16 sm1[];
    __nv_bfloat16* sAhi = sm1;             // 2*5120
    __nv_bfloat16* sAlo = sm1 + 10240;
    __nv_bfloat16* sBhi = sm1 + 20480;     // 2*10240
    __nv_bfloat16* sBlo = sm1 + 40960;     // total 61440 elems = 122880 B

    const int tid = threadIdx.x;
    const int g = blockIdx.z;
    const int row0 = blockIdx.x * 128;
    const float* x  = (g == 0) ? xA  : (g == 1) ? xS  : xB;
    const float* b1 = (g == 0) ? b1A : (g == 1) ? b1S : b1B;
    const __nv_bfloat16* WpHi = g_Wp_hi + (size_t)g * 256 * 1024;
    const __nv_bfloat16* WpLo = g_Wp_lo + (size_t)g * 256 * 1024;

    const int lane = tid & 31, wid = tid >> 5;
    const int gid = lane >> 2, quad = lane & 3;
    const int wm = wid & 3, wn = wid >> 2;   // 4 x M32, 2 x N128

    float acc[2][16][4];
    #pragma unroll
    for (int mt = 0; mt < 2; mt++)
        #pragma unroll
        for (int nt = 0; nt < 16; nt++)
            #pragma unroll
            for (int q = 0; q < 4; q++) acc[mt][nt][q] = 0.f;

    float4 areg[4];

    auto loadA = [&](int kt) {
        int k0 = kt * 32;
        #pragma unroll
        for (int i = 0; i < 4; i++) {
            int idx = tid + i * 256;       // 0..1023
            int r = idx >> 3, c = idx & 7; // k = c*4
            areg[i] = *reinterpret_cast<const float4*>(x + (size_t)(row0 + r) * 1024 + k0 + c * 4);
        }
    };
    auto storeA = [&](int buf) {
        #pragma unroll
        for (int i = 0; i < 4; i++) {
            int idx = tid + i * 256;
            int r = idx >> 3, c = idx & 7;
            float4 f = areg[i];
            __nv_bfloat16 h0 = __float2bfloat16(f.x), h1 = __float2bfloat16(f.y);
            __nv_bfloat16 h2 = __float2bfloat16(f.z), h3 = __float2bfloat16(f.w);
            __nv_bfloat162 H0; H0.x = h0; H0.y = h1;
            __nv_bfloat162 H1; H1.x = h2; H1.y = h3;
            __nv_bfloat162 L0, L1;
            L0.x = __float2bfloat16(f.x - __bfloat162float(h0));
            L0.y = __float2bfloat16(f.y - __bfloat162float(h1));
            L1.x = __float2bfloat16(f.z - __bfloat162float(h2));
            L1.y = __float2bfloat16(f.w - __bfloat162float(h3));
            int off = buf * A_BUF + r * 40 + c * 4;
            reinterpret_cast<__nv_bfloat162*>(sAhi + off)[0] = H0;
            reinterpret_cast<__nv_bfloat162*>(sAhi + off)[1] = H1;
            reinterpret_cast<__nv_bfloat162*>(sAlo + off)[0] = L0;
            reinterpret_cast<__nv_bfloat162*>(sAlo + off)[1] = L1;
        }
    };
    auto loadB = [&](int kt, int buf) {
        int k0 = kt * 32;
        #pragma unroll
        for (int i = 0; i < 8; i++) {
            int idx = tid + i * 256;       // 0..2047; first 1024 hi, next 1024 lo
            int sel = idx >> 10;
            int j = idx & 1023;
            int n = j >> 2, c = j & 3;     // k = c*8
            const __nv_bfloat16* src = (sel ? WpLo : WpHi) + (size_t)n * 1024 + k0 + c * 8;
            __nv_bfloat16* dst = (sel ? sBlo : sBhi) + buf * B_BUF + n * 40 + c * 8;
            cp16(dst, src);
        }
    };
    auto compute = [&](int buf) {
        const __nv_bfloat16* Ah = sAhi + buf * A_BUF;
        const __nv_bfloat16* Al = sAlo + buf * A_BUF;
        const __nv_bfloat16* Bh = sBhi + buf * B_BUF;
        const __nv_bfloat16* Bl = sBlo + buf * B_BUF;
        #pragma unroll
        for (int ks = 0; ks < 2; ks++) {
            int kb = ks * 16;
            unsigned ah[2][4], al[2][4];
            #pragma unroll
            for (int mt = 0; mt < 2; mt++) {
                int r = wm * 32 + mt * 16 + gid;
                ah[mt][0] = ld_u32(Ah + (r)     * 40 + kb     + quad * 2);
                ah[mt][1] = ld_u32(Ah + (r + 8) * 40 + kb     + quad * 2);
                ah[mt][2] = ld_u32(Ah + (r)     * 40 + kb + 8 + quad * 2);
                ah[mt][3] = ld_u32(Ah + (r + 8) * 40 + kb + 8 + quad * 2);
                al[mt][0] = ld_u32(Al + (r)     * 40 + kb     + quad * 2);
                al[mt][1] = ld_u32(Al + (r + 8) * 40 + kb     + quad * 2);
                al[mt][2] = ld_u32(Al + (r)     * 40 + kb + 8 + quad * 2);
                al[mt][3] = ld_u32(Al + (r + 8) * 40 + kb + 8 + quad * 2);
            }
            #pragma unroll
            for (int nt = 0; nt < 16; nt++) {
                int n = wn * 128 + nt * 8 + gid;
                unsigned bh0 = ld_u32(Bh + n * 40 + kb     + quad * 2);
                unsigned bh1 = ld_u32(Bh + n * 40 + kb + 8 + quad * 2);
                unsigned bl0 = ld_u32(Bl + n * 40 + kb     + quad * 2);
                unsigned bl1 = ld_u32(Bl + n * 40 + kb + 8 + quad * 2);
                #pragma unroll
                for (int mt = 0; mt < 2; mt++) {
                    mma_bf16(acc[mt][nt], ah[mt], bh0, bh1);
                    mma_bf16(acc[mt][nt], ah[mt], bl0, bl1);
                    mma_bf16(acc[mt][nt], al[mt], bh0, bh1);
                }
            }
        }
    };

    // prologue
    loadA(0);
    loadB(0, 0);
    cp_commit();
    storeA(0);
    cp_wait0();
    __syncthreads();

    #pragma unroll 1
    for (int kt = 0; kt < 32; kt++) {
        int buf = kt & 1;
        if (kt < 31) {
            loadA(kt + 1);
            loadB(kt + 1, buf ^ 1);
            cp_commit();
        }
        compute(buf);
        if (kt < 31) {
            storeA(buf ^ 1);
            cp_wait0();
        }
        __syncthreads();
    }

    // epilogue: bias + relu, split-store h
    __nv_bfloat16* Hhi = g_h_hi + (size_t)g * NB * 256;
    __nv_bfloat16* Hlo = g_h_lo + (size_t)g * NB * 256;
    #pragma unroll
    for (int mt = 0; mt < 2; mt++) {
        #pragma unroll
        for (int nt = 0; nt < 16; nt++) {
            int col = wn * 128 + nt * 8 + quad * 2;
            float2 bv = *reinterpret_cast<const float2*>(b1 + col);
            #pragma unroll
            for (int p = 0; p < 2; p++) {
                int row = row0 + wm * 32 + mt * 16 + gid + p * 8;
                float v0 = fmaxf(acc[mt][nt][p * 2 + 0] + bv.x, 0.f);
                float v1 = fmaxf(acc[mt][nt][p * 2 + 1] + bv.y, 0.f);
                __nv_bfloat16 h0 = __float2bfloat16(v0);
                __nv_bfloat16 h1 = __float2bfloat16(v1);
                __nv_bfloat162 PH; PH.x = h0; PH.y = h1;
                __nv_bfloat162 PL;
                PL.x = __float2bfloat16(v0 - __bfloat162float(h0));
                PL.y = __float2bfloat16(v1 - __bfloat162float(h1));
                size_t base = (size_t)row * 256 + col;
                *reinterpret_cast<__nv_bfloat162*>(Hhi + base) = PH;
                *reinterpret_cast<__nv_bfloat162*>(Hlo + base) = PL;
            }
        }
    }
}

// ---------- layer 2 + gate combine ----------
__global__ __launch_bounds__(256, 1)
void layer2_kernel(const float* __restrict__ b2A, const float* __restrict__ b2S,
                   const float* __restrict__ b2B, float* __restrict__ out)
{
    __shared__ __nv_bfloat16 sh[2 * 64 * 72];  // hi at 0, lo at 4608
    __shared__ __nv_bfloat16 sw[2 * 64 * 72];
    __shared__ float sg[3][64][12];

    const int tid = threadIdx.x;
    const int row0 = blockIdx.x * 64;
    const int d0 = blockIdx.y * 64;
    const int lane = tid & 31, wid = tid >> 5;
    const int gid = lane >> 2, quad = lane & 3;
    const int wm = wid & 1, wn = wid >> 1;   // 2 x M32, 4 x N16

    for (int i = tid; i < 3 * 64 * 12; i += 256) {
        int gg = i / 768;
        int r = (i / 12) & 63;
        int j = i % 12;
        sg[gg][r][j] = g_gates[((size_t)gg * NB + row0 + r) * 12 + j];
    }

    float oA[2][2][4], oS[2][2][4], oB[2][2][4];
    #pragma unroll
    for (int mt = 0; mt < 2; mt++)
        #pragma unroll
        for (int nt = 0; nt < 2; nt++)
            #pragma unroll
            for (int q = 0; q < 4; q++) { oA[mt][nt][q] = 0.f; oS[mt][nt][q] = 0.f; oB[mt][nt][q] = 0.f; }

    __syncthreads();

    #pragma unroll 1
    for (int ge = 0; ge < 12; ge++) {
        int g = ge >> 2, e = ge & 3;
        const __nv_bfloat16* Hhi = g_h_hi + (size_t)g * NB * 256;
        const __nv_bfloat16* Hlo = g_h_lo + (size_t)g * NB * 256;
        const __nv_bfloat16* Whi = g_W2p_hi + ((size_t)(g * 4 + e) * 256 + d0) * 64;
        const __nv_bfloat16* Wlo = g_W2p_lo + ((size_t)(g * 4 + e) * 256 + d0) * 64;
        #pragma unroll
        for (int i = 0; i < 2; i++) {
            int idx = tid + i * 256;       // 0..511
            int r = idx >> 3, c = idx & 7; // k = c*8
            cp16(sh + r * 72 + c * 8,        Hhi + (size_t)(row0 + r) * 256 + e * 64 + c * 8);
            cp16(sh + 4608 + r * 72 + c * 8, Hlo + (size_t)(row0 + r) * 256 + e * 64 + c * 8);
            cp16(sw + r * 72 + c * 8,        Whi + (size_t)r * 64 + c * 8);
            cp16(sw + 4608 + r * 72 + c * 8, Wlo + (size_t)r * 64 + c * 8);
        }
        cp_commit();
        cp_wait0();
        __syncthreads();

        float t[2][2][4];
        #pragma unroll
        for (int mt = 0; mt < 2; mt++)
            #pragma unroll
            for (int nt = 0; nt < 2; nt++)
                #pragma unroll
                for (int q = 0; q < 4; q++) t[mt][nt][q] = 0.f;

        #pragma unroll
        for (int ks = 0; ks < 4; ks++) {
            int kb = ks * 16;
            unsigned ah[2][4], al[2][4];
            #pragma unroll
            for (int mt = 0; mt < 2; mt++) {
                int r = wm * 32 + mt * 16 + gid;
                ah[mt][0] = ld_u32(sh + (r)     * 72 + kb     + quad * 2);
                ah[mt][1] = ld_u32(sh + (r + 8) * 72 + kb     + quad * 2);
                ah[mt][2] = ld_u32(sh + (r)     * 72 + kb + 8 + quad * 2);
                ah[mt][3] = ld_u32(sh + (r + 8) * 72 + kb + 8 + quad * 2);
                al[mt][0] = ld_u32(sh + 4608 + (r)     * 72 + kb     + quad * 2);
                al[mt][1] = ld_u32(sh + 4608 + (r + 8) * 72 + kb     + quad * 2);
                al[mt][2] = ld_u32(sh + 4608 + (r)     * 72 + kb + 8 + quad * 2);
                al[mt][3] = ld_u32(sh + 4608 + (r + 8) * 72 + kb + 8 + quad * 2);
            }
            #pragma unroll
            for (int nt = 0; nt < 2; nt++) {
                int n = wn * 16 + nt * 8 + gid;
                unsigned bh0 = ld_u32(sw + n * 72 + kb     + quad * 2);
                unsigned bh1 = ld_u32(sw + n * 72 + kb + 8 + quad * 2);
                unsigned bl0 = ld_u32(sw + 4608 + n * 72 + kb     + quad * 2);
                unsigned bl1 = ld_u32(sw + 4608 + n * 72 + kb + 8 + quad * 2);
                #pragma unroll
                for (int mt = 0; mt < 2; mt++) {
                    mma_bf16(t[mt][nt], ah[mt], bh0, bh1);
                    mma_bf16(t[mt][nt], ah[mt], bl0, bl1);
                    mma_bf16(t[mt][nt], al[mt], bh0, bh1);
                }
            }
        }

        const float* b2 = (g == 0) ? b2A : (g == 1) ? b2S : b2B;
        #pragma unroll
        for (int mt = 0; mt < 2; mt++) {
            #pragma unroll
            for (int nt = 0; nt < 2; nt++) {
                int col = wn * 16 + nt * 8 + quad * 2;
                float2 bv = *reinterpret_cast<const float2*>(b2 + e * 256 + d0 + col);
                #pragma unroll
                for (int p = 0; p < 2; p++) {
                    int r = wm * 32 + mt * 16 + gid + p * 8;  // local row
                    float v0 = fmaxf(t[mt][nt][p * 2 + 0] + bv.x, 0.f);
                    float v1 = fmaxf(t[mt][nt][p * 2 + 1] + bv.y, 0.f);
                    if (g == 0) {
                        float ga = sg[0][r][e], gs = sg[1][r][e];
                        oA[mt][nt][p * 2 + 0] += ga * v0; oA[mt][nt][p * 2 + 1] += ga * v1;
                        oS[mt][nt][p * 2 + 0] += gs * v0; oS[mt][nt][p * 2 + 1] += gs * v1;
                    } else if (g == 1) {
                        float ga = sg[0][r][4 + e], gs = sg[1][r][4 + e], gb = sg[2][r][4 + e];
                        oA[mt][nt][p * 2 + 0] += ga * v0; oA[mt][nt][p * 2 + 1] += ga * v1;
                        oS[mt][nt][p * 2 + 0] += gs * v0; oS[mt][nt][p * 2 + 1] += gs * v1;
                        oB[mt][nt][p * 2 + 0] += gb * v0; oB[mt][nt][p * 2 + 1] += gb * v1;
                    } else {
                        float gs = sg[1][r][8 + e], gb = sg[2][r][e];
                        oS[mt][nt][p * 2 + 0] += gs * v0; oS[mt][nt][p * 2 + 1] += gs * v1;
                        oB[mt][nt][p * 2 + 0] += gb * v0; oB[mt][nt][p * 2 + 1] += gb * v1;
                    }
                }
            }
        }
        __syncthreads();
    }

    // write outA | outS | outB
    #pragma unroll
    for (int mt = 0; mt < 2; mt++) {
        #pragma unroll
        for (int nt = 0; nt < 2; nt++) {
            int col = d0 + wn * 16 + nt * 8 + quad * 2;
            #pragma unroll
            for (int p = 0; p < 2; p++) {
                int row = row0 + wm * 32 + mt * 16 + gid + p * 8;
                size_t base = (size_t)row * 256 + col;
                float2 vA; vA.x = oA[mt][nt][p * 2]; vA.y = oA[mt][nt][p * 2 + 1];
                float2 vS; vS.x = oS[mt][nt][p * 2]; vS.y = oS[mt][nt][p * 2 + 1];
                float2 vB; vB.x = oB[mt][nt][p * 2]; vB.y = oB[mt][nt][p * 2 + 1];
                *reinterpret_cast<float2*>(out + base) = vA;
                *reinterpret_cast<float2*>(out + (size_t)NB * 256 + base) = vS;
                *reinterpret_cast<float2*>(out + 2ull * NB * 256 + base) = vB;
            }
        }
    }
}

// ---------- launch ----------
extern "C" void kernel_launch(void* const* d_in, const int* in_sizes, int n_in,
                              void* d_out, int out_size)
{
    const float* xA  = (const float*)d_in[0];
    const float* xS  = (const float*)d_in[1];
    const float* xB  = (const float*)d_in[2];
    const float* W1A = (const float*)d_in[3];
    const float* b1A = (const float*)d_in[4];
    const float* W2A = (const float*)d_in[5];
    const float* b2A = (const float*)d_in[6];
    const float* W1S = (const float*)d_in[7];
    const float* b1S = (const float*)d_in[8];
    const float* W2S = (const float*)d_in[9];
    const float* b2S = (const float*)d_in[10];
    const float* W1B = (const float*)d_in[11];
    const float* b1B = (const float*)d_in[12];
    const float* W2B = (const float*)d_in[13];
    const float* b2B = (const float*)d_in[14];
    const float* WgA = (const float*)d_in[15];
    const float* bgA = (const float*)d_in[16];
    const float* WgB = (const float*)d_in[17];
    const float* bgB = (const float*)d_in[18];
    const float* WgS = (const float*)d_in[19];
    const float* bgS = (const float*)d_in[20];
    float* out = (float*)d_out;

    pack_w1_kernel<<<(3 * 256 * 1024 + 255) / 256, 256>>>(W1A, W1S, W1B);
    pack_w2_kernel<<<(3 * 4 * 256 * 64 + 255) / 256, 256>>>(W2A, W2S, W2B);
    gate_kernel<<<dim3(NB / 64, 1, 3), 256>>>(xA, xS, xB, WgA, bgA, WgS, bgS, WgB, bgB);

    cudaFuncSetAttribute(layer1_kernel, cudaFuncAttributeMaxDynamicSharedMemorySize, 122880);
    layer1_kernel<<<dim3(NB / 128, 1, 3), 256, 122880>>>(xA, xS, xB, b1A, b1S, b1B);

    layer2_kernel<<<dim3(NB / 64, 256 / 64), 256>>>(b2A, b2S, b2B, out);
}

// round 7
// speedup vs baseline: 1.0563x; 1.0563x over previous
#include <cuda_runtime.h>
#include <cuda_bf16.h>
#include <cstdint>

#define NB 16384

__device__ __nv_bfloat16 g_Wp_hi[3 * 256 * 1024];
__device__ __nv_bfloat16 g_Wp_lo[3 * 256 * 1024];
__device__ __nv_bfloat16 g_W2p_hi[3 * 4 * 256 * 64];
__device__ __nv_bfloat16 g_W2p_lo[3 * 4 * 256 * 64];
__device__ __nv_bfloat16 g_h_hi[3ull * NB * 256];
__device__ __nv_bfloat16 g_h_lo[3ull * NB * 256];
__device__ float         g_gates[3ull * NB * 12];

__device__ __forceinline__ uint32_t smem_u32(const void* p) {
    uint32_t a;
    asm("{ .reg .u64 t; cvta.to.shared.u64 t, %1; cvt.u32.u64 %0, t; }" : "=r"(a) : "l"(p));
    return a;
}
__device__ __forceinline__ void cp16s(uint32_t dst, const void* src) {
    asm volatile("cp.async.cg.shared.global [%0], [%1], 16;\n" :: "r"(dst), "l"(src));
}
__device__ __forceinline__ void cp16(void* dst, const void* src) { cp16s(smem_u32(dst), src); }
__device__ __forceinline__ void cp_commit() { asm volatile("cp.async.commit_group;\n"); }
__device__ __forceinline__ void cp_wait0()  { asm volatile("cp.async.wait_group 0;\n"); }
__device__ __forceinline__ void cp_wait1()  { asm volatile("cp.async.wait_group 1;\n"); }

__device__ __forceinline__ void ldsm4(unsigned* r, uint32_t a) {
    asm volatile("ldmatrix.sync.aligned.m8n8.x4.shared.b16 {%0,%1,%2,%3}, [%4];"
        : "=r"(r[0]), "=r"(r[1]), "=r"(r[2]), "=r"(r[3]) : "r"(a));
}
__device__ __forceinline__ void mma_bf16(float* c, const unsigned* a, unsigned b0, unsigned b1) {
    asm volatile(
        "mma.sync.aligned.m16n8k16.row.col.f32.bf16.bf16.f32 "
        "{%0,%1,%2,%3}, {%4,%5,%6,%7}, {%8,%9}, {%0,%1,%2,%3};\n"
        : "+f"(c[0]), "+f"(c[1]), "+f"(c[2]), "+f"(c[3])
        : "r"(a[0]), "r"(a[1]), "r"(a[2]), "r"(a[3]), "r"(b0), "r"(b1));
}

// ---------- packs ----------
__global__ void pack_w1_kernel(const float* __restrict__ W1A, const float* __restrict__ W1S,
                               const float* __restrict__ W1B)
{
    int idx = blockIdx.x * blockDim.x + threadIdx.x;
    if (idx >= 3 * 256 * 1024) return;
    int k = idx & 1023, n = (idx >> 10) & 255, g = idx >> 18;
    const float* W1 = (g == 0) ? W1A : (g == 1) ? W1S : W1B;
    float w = W1[((size_t)(n >> 6) * 1024 + k) * 64 + (n & 63)];
    __nv_bfloat16 hi = __float2bfloat16(w);
    g_Wp_hi[idx] = hi;
    g_Wp_lo[idx] = __float2bfloat16(w - __bfloat162float(hi));
}
__global__ void pack_w2_kernel(const float* __restrict__ W2A, const float* __restrict__ W2S,
                               const float* __restrict__ W2B)
{
    int idx = blockIdx.x * blockDim.x + threadIdx.x;
    if (idx >= 3 * 4 * 256 * 64) return;
    int k = idx & 63, d = (idx >> 6) & 255, e = (idx >> 14) & 3, g = idx >> 16;
    const float* W2 = (g == 0) ? W2A : (g == 1) ? W2S : W2B;
    float w = W2[((size_t)e * 64 + k) * 256 + d];
    __nv_bfloat16 hi = __float2bfloat16(w);
    g_W2p_hi[idx] = hi;
    g_W2p_lo[idx] = __float2bfloat16(w - __bfloat162float(hi));
}

// ---------- gates: softmax(x @ Wg + bg), float4 + 2-row blocking ----------
__global__ __launch_bounds__(256)
void gate_kernel(const float* __restrict__ xA, const float* __restrict__ xS,
                 const float* __restrict__ xB,
                 const float* __restrict__ WgA, const float* __restrict__ bgA,
                 const float* __restrict__ WgS, const float* __restrict__ bgS,
                 const float* __restrict__ WgB, const float* __restrict__ bgB)
{
    __shared__ float sWg[12][1024];
    const int g = blockIdx.z;
    const int row0 = blockIdx.x * 64;
    const float* x  = (g == 0) ? xA  : (g == 1) ? xS  : xB;
    const float* Wg = (g == 0) ? WgA : (g == 1) ? WgS : WgB;
    const float* bg = (g == 0) ? bgA : (g == 1) ? bgS : bgB;
    const int G = (g == 1) ? 12 : 8;
    const int tid = threadIdx.x, lane = tid & 31, wid = tid >> 5;

    for (int i = tid; i < 12 * 1024; i += 256) {
        int j = i >> 10, k = i & 1023;
        sWg[j][k] = (j < G) ? Wg[(size_t)k * G + j] : 0.f;
    }
    __syncthreads();

    for (int rp = 0; rp < 4; rp++) {
        int r0 = row0 + wid * 8 + rp * 2;
        float a0[12], a1[12];
        #pragma unroll
        for (int j = 0; j < 12; j++) { a0[j] = 0.f; a1[j] = 0.f; }
        const float* xr0 = x + (size_t)r0 * 1024;
        const float* xr1 = xr0 + 1024;
        for (int k4 = lane * 4; k4 < 1024; k4 += 128) {
            float4 v0 = *reinterpret_cast<const float4*>(xr0 + k4);
            float4 v1 = *reinterpret_cast<const float4*>(xr1 + k4);
            #pragma unroll
            for (int j = 0; j < 12; j++) {
                float4 wv = *reinterpret_cast<const float4*>(&sWg[j][k4]);
                a0[j] += v0.x * wv.x + v0.y * wv.y + v0.z * wv.z + v0.w * wv.w;
                a1[j] += v1.x * wv.x + v1.y * wv.y + v1.z * wv.z + v1.w * wv.w;
            }
        }
        #pragma unroll
        for (int j = 0; j < 12; j++) {
            #pragma unroll
            for (int off = 16; off > 0; off >>= 1) {
                a0[j] += __shfl_xor_sync(0xffffffffu, a0[j], off);
                a1[j] += __shfl_xor_sync(0xffffffffu, a1[j], off);
            }
        }
        if (lane == 0) {
            for (int rr = 0; rr < 2; rr++) {
                float* ac = rr ? a1 : a0;
                float lg[12], m = -1e30f;
                for (int j = 0; j < G; j++) { lg[j] = ac[j] + bg[j]; m = fmaxf(m, lg[j]); }
                float s = 0.f;
                for (int j = 0; j < G; j++) { lg[j] = expf(lg[j] - m); s += lg[j]; }
                float inv = 1.f / s;
                float* dst = g_gates + ((size_t)g * NB + r0 + rr) * 12;
                for (int j = 0; j < G; j++) dst[j] = lg[j] * inv;
            }
        }
    }
}

// ---------- layer 1: HMMA + ldmatrix ----------
#define A_BUF 5120   // 128*40 bf16 per buffer
#define B_BUF 10240  // 256*40

__global__ __launch_bounds__(256, 1)
void layer1_kernel(const float* __restrict__ xA, const float* __restrict__ xS,
                   const float* __restrict__ xB,
                   const float* __restrict__ b1A, const float* __restrict__ b1S,
                   const float* __restrict__ b1B)
{
    extern __shared__ __nv_bfloat16 sm1[];
    __nv_bfloat16* sAhi = sm1;
    __nv_bfloat16* sAlo = sm1 + 10240;
    __nv_bfloat16* sBhi = sm1 + 20480;
    __nv_bfloat16* sBlo = sm1 + 40960;

    const int tid = threadIdx.x;
    const int g = blockIdx.z;
    const int row0 = blockIdx.x * 128;
    const float* x  = (g == 0) ? xA  : (g == 1) ? xS  : xB;
    const float* b1 = (g == 0) ? b1A : (g == 1) ? b1S : b1B;
    const __nv_bfloat16* WpHi = g_Wp_hi + (size_t)g * 256 * 1024;
    const __nv_bfloat16* WpLo = g_Wp_lo + (size_t)g * 256 * 1024;

    const int lane = tid & 31, wid = tid >> 5;
    const int gid = lane >> 2, quad = lane & 3;
    const int wm = wid & 3, wn = wid >> 2;

    // ldmatrix lane->address components
    const int a_row = (lane & 7) + ((lane >> 3) & 1) * 8;   // + wm*32 + mt*16
    const int a_col = (lane >> 4) * 8;                      // + kb
    const int b_row = (lane & 7) + (lane >> 4) * 8;         // + wn*128 + ntp*16
    const int b_col = ((lane >> 3) & 1) * 8;                // + kb

    float acc[2][16][4];
    #pragma unroll
    for (int mt = 0; mt < 2; mt++)
        #pragma unroll
        for (int nt = 0; nt < 16; nt++)
            #pragma unroll
            for (int q = 0; q < 4; q++) acc[mt][nt][q] = 0.f;

    float4 areg[4];
    auto loadA = [&](int kt) {
        int k0 = kt * 32;
        #pragma unroll
        for (int i = 0; i < 4; i++) {
            int idx = tid + i * 256;
            int r = idx >> 3, c = idx & 7;
            areg[i] = *reinterpret_cast<const float4*>(x + (size_t)(row0 + r) * 1024 + k0 + c * 4);
        }
    };
    auto storeA = [&](int buf) {
        #pragma unroll
        for (int i = 0; i < 4; i++) {
            int idx = tid + i * 256;
            int r = idx >> 3, c = idx & 7;
            float4 f = areg[i];
            __nv_bfloat16 h0 = __float2bfloat16(f.x), h1 = __float2bfloat16(f.y);
            __nv_bfloat16 h2 = __float2bfloat16(f.z), h3 = __float2bfloat16(f.w);
            __nv_bfloat162 H0; H0.x = h0; H0.y = h1;
            __nv_bfloat162 H1; H1.x = h2; H1.y = h3;
            __nv_bfloat162 L0, L1;
            L0.x = __float2bfloat16(f.x - __bfloat162float(h0));
            L0.y = __float2bfloat16(f.y - __bfloat162float(h1));
            L1.x = __float2bfloat16(f.z - __bfloat162float(h2));
            L1.y = __float2bfloat16(f.w - __bfloat162float(h3));
            int off = buf * A_BUF + r * 40 + c * 4;
            reinterpret_cast<__nv_bfloat162*>(sAhi + off)[0] = H0;
            reinterpret_cast<__nv_bfloat162*>(sAhi + off)[1] = H1;
            reinterpret_cast<__nv_bfloat162*>(sAlo + off)[0] = L0;
            reinterpret_cast<__nv_bfloat162*>(sAlo + off)[1] = L1;
        }
    };
    auto loadB = [&](int kt, int buf) {
        int k0 = kt * 32;
        #pragma unroll
        for (int i = 0; i < 8; i++) {
            int idx = tid + i * 256;
            int sel = idx >> 10;
            int j = idx & 1023;
            int n = j >> 2, c = j & 3;
            const __nv_bfloat16* src = (sel ? WpLo : WpHi) + (size_t)n * 1024 + k0 + c * 8;
            __nv_bfloat16* dst = (sel ? sBlo : sBhi) + buf * B_BUF + n * 40 + c * 8;
            cp16(dst, src);
        }
    };
    auto compute = [&](int buf) {
        const __nv_bfloat16* Ah = sAhi + buf * A_BUF;
        const __nv_bfloat16* Al = sAlo + buf * A_BUF;
        const __nv_bfloat16* Bh = sBhi + buf * B_BUF;
        const __nv_bfloat16* Bl = sBlo + buf * B_BUF;
        #pragma unroll
        for (int ks = 0; ks < 2; ks++) {
            int kb = ks * 16;
            unsigned ah[2][4], al[2][4];
            #pragma unroll
            for (int mt = 0; mt < 2; mt++) {
                int r = wm * 32 + mt * 16 + a_row;
                ldsm4(ah[mt], smem_u32(Ah + r * 40 + kb + a_col));
                ldsm4(al[mt], smem_u32(Al + r * 40 + kb + a_col));
            }
            #pragma unroll
            for (int ntp = 0; ntp < 8; ntp++) {
                int n = wn * 128 + ntp * 16 + b_row;
                unsigned bh[4], bl[4];
                ldsm4(bh, smem_u32(Bh + n * 40 + kb + b_col));
                ldsm4(bl, smem_u32(Bl + n * 40 + kb + b_col));
                #pragma unroll
                for (int mt = 0; mt < 2; mt++) {
                    mma_bf16(acc[mt][2 * ntp],     ah[mt], bh[0], bh[1]);
                    mma_bf16(acc[mt][2 * ntp],     ah[mt], bl[0], bl[1]);
                    mma_bf16(acc[mt][2 * ntp],     al[mt], bh[0], bh[1]);
                    mma_bf16(acc[mt][2 * ntp + 1], ah[mt], bh[2], bh[3]);
                    mma_bf16(acc[mt][2 * ntp + 1], ah[mt], bl[2], bl[3]);
                    mma_bf16(acc[mt][2 * ntp + 1], al[mt], bh[2], bh[3]);
                }
            }
        }
    };

    loadA(0);
    loadB(0, 0);
    cp_commit();
    storeA(0);
    cp_wait0();
    __syncthreads();

    #pragma unroll 1
    for (int kt = 0; kt < 32; kt++) {
        int buf = kt & 1;
        if (kt < 31) {
            loadA(kt + 1);
            loadB(kt + 1, buf ^ 1);
            cp_commit();
        }
        compute(buf);
        if (kt < 31) {
            storeA(buf ^ 1);
            cp_wait0();
        }
        __syncthreads();
    }

    __nv_bfloat16* Hhi = g_h_hi + (size_t)g * NB * 256;
    __nv_bfloat16* Hlo = g_h_lo + (size_t)g * NB * 256;
    #pragma unroll
    for (int mt = 0; mt < 2; mt++) {
        #pragma unroll
        for (int nt = 0; nt < 16; nt++) {
            int col = wn * 128 + nt * 8 + quad * 2;
            float2 bv = *reinterpret_cast<const float2*>(b1 + col);
            #pragma unroll
            for (int p = 0; p < 2; p++) {
                int row = row0 + wm * 32 + mt * 16 + gid + p * 8;
                float v0 = fmaxf(acc[mt][nt][p * 2 + 0] + bv.x, 0.f);
                float v1 = fmaxf(acc[mt][nt][p * 2 + 1] + bv.y, 0.f);
                __nv_bfloat16 h0 = __float2bfloat16(v0);
                __nv_bfloat16 h1 = __float2bfloat16(v1);
                __nv_bfloat162 PH; PH.x = h0; PH.y = h1;
                __nv_bfloat162 PL;
                PL.x = __float2bfloat16(v0 - __bfloat162float(h0));
                PL.y = __float2bfloat16(v1 - __bfloat162float(h1));
                size_t base = (size_t)row * 256 + col;
                *reinterpret_cast<__nv_bfloat162*>(Hhi + base) = PH;
                *reinterpret_cast<__nv_bfloat162*>(Hlo + base) = PL;
            }
        }
    }
}

// ---------- layer 2 + combine: double-buffered, grid (d fastest) ----------
// dyn smem: sh 2st x 9216 bf16, sw 2st x 9216 bf16, sg 3*64*12 floats
#define L2_SH 0
#define L2_SW 36864
#define L2_SG 73728
#define L2_SM 82944
#define L2_STG 18432  // bytes per stage (hi 9216B + lo 9216B)

__global__ __launch_bounds__(256, 1)
void layer2_kernel(const float* __restrict__ b2A, const float* __restrict__ b2S,
                   const float* __restrict__ b2B, float* __restrict__ out)
{
    extern __shared__ char sm2[];
    __nv_bfloat16* shb = reinterpret_cast<__nv_bfloat16*>(sm2 + L2_SH);
    __nv_bfloat16* swb = reinterpret_cast<__nv_bfloat16*>(sm2 + L2_SW);
    float* sg = reinterpret_cast<float*>(sm2 + L2_SG);   // [3][64][12]

    const int tid = threadIdx.x;
    const int d0 = blockIdx.x * 64;
    const int row0 = blockIdx.y * 64;
    const int lane = tid & 31, wid = tid >> 5;
    const int gid = lane >> 2, quad = lane & 3;
    const int wm = wid & 1, wn = wid >> 1;

    const int a_row = (lane & 7) + ((lane >> 3) & 1) * 8;
    const int a_col = (lane >> 4) * 8;
    const int b_row = (lane & 7) + (lane >> 4) * 8;
    const int b_col = ((lane >> 3) & 1) * 8;

    for (int i = tid; i < 3 * 64 * 12; i += 256) {
        int gg = i / 768, r = (i / 12) & 63, j = i % 12;
        sg[(gg * 64 + r) * 12 + j] = g_gates[((size_t)gg * NB + row0 + r) * 12 + j];
    }

    auto prefetch = [&](int ge, int s) {
        int g = ge >> 2, e = ge & 3;
        const __nv_bfloat16* Hhi = g_h_hi + (size_t)g * NB * 256;
        const __nv_bfloat16* Hlo = g_h_lo + (size_t)g * NB * 256;
        const __nv_bfloat16* Whi = g_W2p_hi + ((size_t)(g * 4 + e) * 256 + d0) * 64;
        const __nv_bfloat16* Wlo = g_W2p_lo + ((size_t)(g * 4 + e) * 256 + d0) * 64;
        __nv_bfloat16* shs = shb + s * (L2_STG / 2);
        __nv_bfloat16* sws = swb + s * (L2_STG / 2);
        #pragma unroll
        for (int i = 0; i < 2; i++) {
            int idx = tid + i * 256;
            int r = idx >> 3, c = idx & 7;
            cp16(shs + r * 72 + c * 8,        Hhi + (size_t)(row0 + r) * 256 + e * 64 + c * 8);
            cp16(shs + 4608 + r * 72 + c * 8, Hlo + (size_t)(row0 + r) * 256 + e * 64 + c * 8);
            cp16(sws + r * 72 + c * 8,        Whi + (size_t)r * 64 + c * 8);
            cp16(sws + 4608 + r * 72 + c * 8, Wlo + (size_t)r * 64 + c * 8);
        }
        cp_commit();
    };

    float oA[2][2][4], oS[2][2][4], oB[2][2][4];
    #pragma unroll
    for (int mt = 0; mt < 2; mt++)
        #pragma unroll
        for (int nt = 0; nt < 2; nt++)
            #pragma unroll
            for (int q = 0; q < 4; q++) { oA[mt][nt][q] = 0.f; oS[mt][nt][q] = 0.f; oB[mt][nt][q] = 0.f; }

    prefetch(0, 0);
    __syncthreads();

    #pragma unroll 1
    for (int ge = 0; ge < 12; ge++) {
        int s = ge & 1;
        int g = ge >> 2, e = ge & 3;
        if (ge < 11) { prefetch(ge + 1, s ^ 1); cp_wait1(); }
        else cp_wait0();
        __syncthreads();

        const __nv_bfloat16* shs = shb + s * (L2_STG / 2);
        const __nv_bfloat16* sws = swb + s * (L2_STG / 2);

        float t[2][2][4];
        #pragma unroll
        for (int mt = 0; mt < 2; mt++)
            #pragma unroll
            for (int nt = 0; nt < 2; nt++)
                #pragma unroll
                for (int q = 0; q < 4; q++) t[mt][nt][q] = 0.f;

        #pragma unroll
        for (int ks = 0; ks < 4; ks++) {
            int kb = ks * 16;
            unsigned ah[2][4], al[2][4];
            #pragma unroll
            for (int mt = 0; mt < 2; mt++) {
                int r = wm * 32 + mt * 16 + a_row;
                ldsm4(ah[mt], smem_u32(shs + r * 72 + kb + a_col));
                ldsm4(al[mt], smem_u32(shs + 4608 + r * 72 + kb + a_col));
            }
            // warp covers n = wn*16 .. wn*16+15 -> one ldsm4 pair covers both nt
            int n = wn * 16 + b_row;
            unsigned bh[4], bl[4];
            ldsm4(bh, smem_u32(sws + n * 72 + kb + b_col));
            ldsm4(bl, smem_u32(sws + 4608 + n * 72 + kb + b_col));
            #pragma unroll
            for (int mt = 0; mt < 2; mt++) {
                mma_bf16(t[mt][0], ah[mt], bh[0], bh[1]);
                mma_bf16(t[mt][0], ah[mt], bl[0], bl[1]);
                mma_bf16(t[mt][0], al[mt], bh[0], bh[1]);
                mma_bf16(t[mt][1], ah[mt], bh[2], bh[3]);
                mma_bf16(t[mt][1], ah[mt], bl[2], bl[3]);
                mma_bf16(t[mt][1], al[mt], bh[2], bh[3]);
            }
        }

        const float* b2 = (g == 0) ? b2A : (g == 1) ? b2S : b2B;
        #pragma unroll
        for (int mt = 0; mt < 2; mt++) {
            #pragma unroll
            for (int nt = 0; nt < 2; nt++) {
                int col = wn * 16 + nt * 8 + quad * 2;
                float2 bv = *reinterpret_cast<const float2*>(b2 + e * 256 + d0 + col);
                #pragma unroll
                for (int p = 0; p < 2; p++) {
                    int r = wm * 32 + mt * 16 + gid + p * 8;
                    float v0 = fmaxf(t[mt][nt][p * 2 + 0] + bv.x, 0.f);
                    float v1 = fmaxf(t[mt][nt][p * 2 + 1] + bv.y, 0.f);
                    const float* sgr = sg + (g * 64 + r) * 12;
                    if (g == 0) {
                        float ga = sg[(0 * 64 + r) * 12 + e], gs = sg[(1 * 64 + r) * 12 + e];
                        oA[mt][nt][p * 2 + 0] += ga * v0; oA[mt][nt][p * 2 + 1] += ga * v1;
                        oS[mt][nt][p * 2 + 0] += gs * v0; oS[mt][nt][p * 2 + 1] += gs * v1;
                    } else if (g == 1) {
                        float ga = sg[(0 * 64 + r) * 12 + 4 + e];
                        float gs = sg[(1 * 64 + r) * 12 + 4 + e];
                        float gb = sg[(2 * 64 + r) * 12 + 4 + e];
                        oA[mt][nt][p * 2 + 0] += ga * v0; oA[mt][nt][p * 2 + 1] += ga * v1;
                        oS[mt][nt][p * 2 + 0] += gs * v0; oS[mt][nt][p * 2 + 1] += gs * v1;
                        oB[mt][nt][p * 2 + 0] += gb * v0; oB[mt][nt][p * 2 + 1] += gb * v1;
                    } else {
                        float gs = sg[(1 * 64 + r) * 12 + 8 + e];
                        float gb = sg[(2 * 64 + r) * 12 + e];
                        oS[mt][nt][p * 2 + 0] += gs * v0; oS[mt][nt][p * 2 + 1] += gs * v1;
                        oB[mt][nt][p * 2 + 0] += gb * v0; oB[mt][nt][p * 2 + 1] += gb * v1;
                    }
                    (void)sgr;
                }
            }
        }
        __syncthreads();
    }

    #pragma unroll
    for (int mt = 0; mt < 2; mt++) {
        #pragma unroll
        for (int nt = 0; nt < 2; nt++) {
            int col = d0 + wn * 16 + nt * 8 + quad * 2;
            #pragma unroll
            for (int p = 0; p < 2; p++) {
                int row = row0 + wm * 32 + mt * 16 + gid + p * 8;
                size_t base = (size_t)row * 256 + col;
                float2 vA; vA.x = oA[mt][nt][p * 2]; vA.y = oA[mt][nt][p * 2 + 1];
                float2 vS; vS.x = oS[mt][nt][p * 2]; vS.y = oS[mt][nt][p * 2 + 1];
                float2 vB; vB.x = oB[mt][nt][p * 2]; vB.y = oB[mt][nt][p * 2 + 1];
                *reinterpret_cast<float2*>(out + base) = vA;
                *reinterpret_cast<float2*>(out + (size_t)NB * 256 + base) = vS;
                *reinterpret_cast<float2*>(out + 2ull * NB * 256 + base) = vB;
            }
        }
    }
}

extern "C" void kernel_launch(void* const* d_in, const int* in_sizes, int n_in,
                              void* d_out, int out_size)
{
    const float* xA  = (const float*)d_in[0];
    const float* xS  = (const float*)d_in[1];
    const float* xB  = (const float*)d_in[2];
    const float* W1A = (const float*)d_in[3];
    const float* b1A = (const float*)d_in[4];
    const float* W2A = (const float*)d_in[5];
    const float* b2A = (const float*)d_in[6];
    const float* W1S = (const float*)d_in[7];
    const float* b1S = (const float*)d_in[8];
    const float* W2S = (const float*)d_in[9];
    const float* b2S = (const float*)d_in[10];
    const float* W1B = (const float*)d_in[11];
    const float* b1B = (const float*)d_in[12];
    const float* W2B = (const float*)d_in[13];
    const float* b2B = (const float*)d_in[14];
    const float* WgA = (const float*)d_in[15];
    const float* bgA = (const float*)d_in[16];
    const float* WgB = (const float*)d_in[17];
    const float* bgB = (const float*)d_in[18];
    const float* WgS = (const float*)d_in[19];
    const float* bgS = (const float*)d_in[20];
    float* out = (float*)d_out;

    pack_w1_kernel<<<(3 * 256 * 1024 + 255) / 256, 256>>>(W1A, W1S, W1B);
    pack_w2_kernel<<<(3 * 4 * 256 * 64 + 255) / 256, 256>>>(W2A, W2S, W2B);
    gate_kernel<<<dim3(NB / 64, 1, 3), 256>>>(xA, xS, xB, WgA, bgA, WgS, bgS, WgB, bgB);

    cudaFuncSetAttribute(layer1_kernel, cudaFuncAttributeMaxDynamicSharedMemorySize, 122880);
    layer1_kernel<<<dim3(NB / 128, 1, 3), 256, 122880>>>(xA, xS, xB, b1A, b1S, b1B);

    cudaFuncSetAttribute(layer2_kernel, cudaFuncAttributeMaxDynamicSharedMemorySize, L2_SM);
    layer2_kernel<<<dim3(256 / 64, NB / 64), 256, L2_SM>>>(b2A, b2S, b2B, out);
}